// round 14
// baseline (speedup 1.0000x reference)
#include <cuda_runtime.h>
#include <cstdint>

// VectorQuantizer via legacy mma.sync tf32 GEMM (+ exact fp32 candidate rescore).
// Out (f32): [ zq (N*64) | emb_ix as float (N) | vq_loss (1) ].
// K-dimension of SMEM operands stored permuted (j -> 2*(j&3)+(j>>2) within each
// 8-group) so mma fragment pairs {k,k+4} are contiguous float2 -> LDS.64.

#define DDIM 64
#define KCODES 512
#define TPT 64
#define TILES_PER_CTA 8
#define NTHREADS 256
#define MARGIN 1.5f
#define ROWF 72                // row pad: 72 mod 32 = 8 -> conflict-free float2
#define PAIR_CAP 8192

// ---- smem byte offsets ------------------------------------------------------
#define ZEP_OFF    0           // 64 * 72 * 4   = 18432   (permuted)
#define BP_OFF     18432       // 512 * 72 * 4  = 147456  (permuted)
#define NORM_OFF   165888      // 512 f32
#define PV_OFF     167936      // 256 f32
#define VTOK_OFF   168960      // 64 f32
#define TOKMIN_OFF 169216      // 64 u64
#define PAIR_OFF   169728      // 8192 u32
#define CNT_OFF    202496      // i32
#define WSUM_OFF   202500      // 8 f32
#define SMEM_TOTAL 202560

__device__ float g_partial[8192];
__device__ unsigned g_done;    // zero-initialized; self-resetting

__device__ __forceinline__ void mma_tf32(float* c, const uint32_t a[4],
                                         uint32_t b0, uint32_t b1) {
    asm volatile(
        "mma.sync.aligned.m16n8k8.row.col.f32.tf32.tf32.f32 "
        "{%0,%1,%2,%3}, {%4,%5,%6,%7}, {%8,%9}, {%0,%1,%2,%3};"
        : "+f"(c[0]), "+f"(c[1]), "+f"(c[2]), "+f"(c[3])
        : "r"(a[0]), "r"(a[1]), "r"(a[2]), "r"(a[3]), "r"(b0), "r"(b1));
}

extern "C" __global__ void __launch_bounds__(NTHREADS, 1)
vq_main(const float* __restrict__ ze, const float* __restrict__ emb,
        float* __restrict__ zq, float* __restrict__ idxo,
        float* __restrict__ losso, int n, int grid, float lscale)
{
    extern __shared__ __align__(16) char smem[];
    float*    zep    = (float*)(smem + ZEP_OFF);
    float*    bp     = (float*)(smem + BP_OFF);
    float*    norm_s = (float*)(smem + NORM_OFF);
    float*    pv     = (float*)(smem + PV_OFF);
    float*    vtok   = (float*)(smem + VTOK_OFF);
    unsigned long long* tokmin = (unsigned long long*)(smem + TOKMIN_OFF);
    unsigned* pair   = (unsigned*)(smem + PAIR_OFF);
    int*      cnt    = (int*)(smem + CNT_OFF);
    float*    wsum   = (float*)(smem + WSUM_OFF);

    const int tid  = threadIdx.x;
    const int w    = tid >> 5, lane = tid & 31;
    const int g    = lane >> 2, tig = lane & 3;
    const int mg   = w >> 2,   cg  = w & 3;

    // ---- codebook -> SMEM once per CTA, k-permuted, coalesced reads --------
    {
        const float4* src = (const float4*)emb;
        #pragma unroll 4
        for (int i = tid; i < KCODES * 16; i += NTHREADS) {
            int k = i >> 4, seg = i & 15;
            float4 v = src[i];
            float* gp = bp + k * ROWF + (seg >> 1) * 8;
            if ((seg & 1) == 0) { gp[0]=v.x; gp[2]=v.y; gp[4]=v.z; gp[6]=v.w; }
            else                { gp[1]=v.x; gp[3]=v.y; gp[5]=v.z; gp[7]=v.w; }
        }
    }
    __syncthreads();
    // exact fp32 norms (permutation-invariant)
    for (int k = tid; k < KCODES; k += NTHREADS) {
        const float4* row = (const float4*)(bp + k * ROWF);
        float s = 0.f;
        #pragma unroll
        for (int i = 0; i < 16; i++) {
            float4 v = row[i];
            s += v.x * v.x + v.y * v.y + v.z * v.z + v.w * v.w;
        }
        norm_s[k] = s;
    }

    float lsum = 0.f;

    for (int t = 0; t < TILES_PER_CTA; t++) {
        const int gtok0 = (blockIdx.x * TILES_PER_CTA + t) * TPT;

        // ---- ze tile -> SMEM (permuted): warp w owns tokens w*8..w*8+7 -----
        #pragma unroll
        for (int r = 0; r < 8; r++) {
            int tok = w * 8 + r;
            int gt  = gtok0 + tok; if (gt > n - 1) gt = n - 1;
            float2 v = *(const float2*)(ze + (size_t)gt * DDIM + lane * 2);
            int j  = lane * 2;
            int jj = j & 7;
            int p0 = ((jj & 2) << 1) + (jj >> 2);     // perm(jj); pair at p0,p0+2
            float* gd = zep + tok * ROWF + (j >> 3) * 8;
            gd[p0] = v.x; gd[p0 + 2] = v.y;
        }
        if (tid < TPT) tokmin[tid] = ~0ull;
        if (tid == 0)  *cnt = 0;
        __syncthreads();

        // ---- mma: warp tile m32 (tokens mg*32..) x n128 (codes cg*128..) ---
        float acc[2][16][4];
        #pragma unroll
        for (int mt = 0; mt < 2; mt++)
            #pragma unroll
            for (int nt = 0; nt < 16; nt++)
                #pragma unroll
                for (int c = 0; c < 4; c++) acc[mt][nt][c] = 0.f;

        const float* za = zep + (mg * 32 + g) * ROWF + 2 * tig;
        const float* ba = bp  + (cg * 128 + g) * ROWF + 2 * tig;

        #pragma unroll
        for (int kt = 0; kt < 8; kt++) {
            uint32_t a[2][4];
            #pragma unroll
            for (int mt = 0; mt < 2; mt++) {
                float2 x0 = *(const float2*)(za + (mt * 16    ) * ROWF + kt * 8);
                float2 x1 = *(const float2*)(za + (mt * 16 + 8) * ROWF + kt * 8);
                a[mt][0] = __float_as_uint(x0.x);   // k=tig,   row g
                a[mt][1] = __float_as_uint(x1.x);   // k=tig,   row g+8
                a[mt][2] = __float_as_uint(x0.y);   // k=tig+4, row g
                a[mt][3] = __float_as_uint(x1.y);   // k=tig+4, row g+8
            }
            #pragma unroll
            for (int nt = 0; nt < 16; nt++) {
                float2 b = *(const float2*)(ba + nt * 8 * ROWF + kt * 8);
                uint32_t b0 = __float_as_uint(b.x);
                uint32_t b1 = __float_as_uint(b.y);
                mma_tf32(acc[0][nt], a[0], b0, b1);
                mma_tf32(acc[1][nt], a[1], b0, b1);
            }
        }

        // ---- epilogue A: per-row tf32 min ----
        float2 nrm[16];
        #pragma unroll
        for (int nt = 0; nt < 16; nt++)
            nrm[nt] = *(const float2*)(norm_s + cg * 128 + nt * 8 + tig * 2);

        float v[2][2];
        v[0][0] = v[0][1] = v[1][0] = v[1][1] = 3.402823e38f;
        #pragma unroll
        for (int mt = 0; mt < 2; mt++)
            #pragma unroll
            for (int nt = 0; nt < 16; nt++) {
                float s0 = fmaf(-2.f, acc[mt][nt][0], nrm[nt].x);
                float s1 = fmaf(-2.f, acc[mt][nt][1], nrm[nt].y);
                float s2 = fmaf(-2.f, acc[mt][nt][2], nrm[nt].x);
                float s3 = fmaf(-2.f, acc[mt][nt][3], nrm[nt].y);
                v[mt][0] = fminf(v[mt][0], fminf(s0, s1));
                v[mt][1] = fminf(v[mt][1], fminf(s2, s3));
            }
        #pragma unroll
        for (int mt = 0; mt < 2; mt++)
            #pragma unroll
            for (int h = 0; h < 2; h++) {
                float x = v[mt][h];
                x = fminf(x, __shfl_xor_sync(0xffffffffu, x, 1));
                x = fminf(x, __shfl_xor_sync(0xffffffffu, x, 2));
                v[mt][h] = x;
            }
        if (tig == 0) {
            #pragma unroll
            for (int mt = 0; mt < 2; mt++)
                #pragma unroll
                for (int h = 0; h < 2; h++)
                    pv[cg * 64 + mg * 32 + mt * 16 + h * 8 + g] = v[mt][h];
        }
        __syncthreads();
        if (tid < TPT) {
            float m0 = fminf(pv[tid],       pv[64  + tid]);
            float m1 = fminf(pv[128 + tid], pv[192 + tid]);
            vtok[tid] = fminf(m0, m1) + MARGIN;
        }
        __syncthreads();

        // ---- epilogue B: emit candidate (token,code) pairs ----
        float th[2][2];
        #pragma unroll
        for (int mt = 0; mt < 2; mt++)
            #pragma unroll
            for (int h = 0; h < 2; h++)
                th[mt][h] = vtok[mg * 32 + mt * 16 + h * 8 + g];

        #pragma unroll
        for (int mt = 0; mt < 2; mt++)
            #pragma unroll
            for (int nt = 0; nt < 16; nt++) {
                float s[4];
                s[0] = fmaf(-2.f, acc[mt][nt][0], nrm[nt].x);
                s[1] = fmaf(-2.f, acc[mt][nt][1], nrm[nt].y);
                s[2] = fmaf(-2.f, acc[mt][nt][2], nrm[nt].x);
                s[3] = fmaf(-2.f, acc[mt][nt][3], nrm[nt].y);
                bool any = (fminf(s[0], s[1]) < th[mt][0]) ||
                           (fminf(s[2], s[3]) < th[mt][1]);
                unsigned ma = __ballot_sync(0xffffffffu, any);
                if (ma) {
                    #pragma unroll
                    for (int c = 0; c < 4; c++) {
                        bool p = s[c] < th[mt][c >> 1];
                        unsigned m = __ballot_sync(0xffffffffu, p);
                        if (m) {
                            int leader = __ffs(m) - 1;
                            int base = 0;
                            if (lane == leader) base = atomicAdd(cnt, __popc(m));
                            base = __shfl_sync(0xffffffffu, base, leader);
                            if (p) {
                                int r    = __popc(m & ((1u << lane) - 1));
                                int tok  = mg * 32 + mt * 16 + (c >> 1) * 8 + g;
                                int code = cg * 128 + nt * 8 + tig * 2 + (c & 1);
                                if (base + r < PAIR_CAP)
                                    pair[base + r] = (unsigned)((tok << 9) | code);
                            }
                        }
                    }
                }
            }
        __syncthreads();

        // ---- exact fp32 rescore (permuted domain; dot is perm-invariant) ---
        {
            int np = *cnt; if (np > PAIR_CAP) np = PAIR_CAP;
            for (int p = w; p < np; p += 8) {
                unsigned pc = pair[p];
                int tok = pc >> 9, code = pc & 511;
                float2 zz = *(const float2*)(zep + tok  * ROWF + lane * 2);
                float2 ee = *(const float2*)(bp  + code * ROWF + lane * 2);
                float d = zz.x * ee.x + zz.y * ee.y;
                #pragma unroll
                for (int o = 16; o > 0; o >>= 1)
                    d += __shfl_xor_sync(0xffffffffu, d, o);
                if (lane == 0) {
                    float s = fmaf(-2.f, d, norm_s[code]);
                    unsigned u = __float_as_uint(s);
                    u = (u & 0x80000000u) ? ~u : (u | 0x80000000u);
                    unsigned long long enc =
                        ((unsigned long long)u << 32) | (unsigned)code;
                    atomicMin(&tokmin[tok], enc);
                }
            }
        }
        __syncthreads();

        // ---- outputs: zq (e rows from gmem, original order), index, loss ---
        {
            int tok  = tid >> 2;
            int qd   = (tid & 3) * 16;
            int gtok = gtok0 + tok;
            if (gtok < n) {
                int code = (int)(tokmin[tok] & 511ull);
                if ((tid & 3) == 0 && idxo) idxo[gtok] = (float)code;
                const float4* es  = (const float4*)(emb + (size_t)code * DDIM + qd);
                float4*       dst = (float4*)(zq + (size_t)gtok * DDIM + qd);
                const float*  zr  = zep + tok * ROWF;
                #pragma unroll
                for (int i = 0; i < 4; i++) {
                    float4 e4 = es[i];
                    float zl[4];
                    #pragma unroll
                    for (int u2 = 0; u2 < 4; u2++) {
                        int j  = qd + 4 * i + u2;
                        int jj = j & 7;
                        zl[u2] = zr[(j & ~7) + 2 * (jj & 3) + (jj >> 2)];
                    }
                    float q0 = e4.x - zl[0], q1 = e4.y - zl[1];
                    float q2 = e4.z - zl[2], q3 = e4.w - zl[3];
                    lsum += q0 * q0 + q1 * q1 + q2 * q2 + q3 * q3;
                    dst[i] = e4;
                }
            }
        }
        __syncthreads();   // before next tile overwrites zep/tokmin
    }

    // ---- per-CTA loss partial + fused finalize (last CTA) ----
    #pragma unroll
    for (int o = 16; o > 0; o >>= 1)
        lsum += __shfl_xor_sync(0xffffffffu, lsum, o);
    if (lane == 0) wsum[w] = lsum;
    __syncthreads();
    __shared__ unsigned is_last;
    if (tid == 0) {
        float s = 0.f;
        #pragma unroll
        for (int i = 0; i < 8; i++) s += wsum[i];
        g_partial[blockIdx.x] = s;
        __threadfence();
        unsigned prev = atomicAdd(&g_done, 1u);
        is_last = (prev == (unsigned)(grid - 1));
    }
    __syncthreads();
    if (is_last && losso) {
        float s = 0.f;
        for (int i = tid; i < grid; i += NTHREADS) s += g_partial[i];
        #pragma unroll
        for (int o = 16; o > 0; o >>= 1)
            s += __shfl_xor_sync(0xffffffffu, s, o);
        if (lane == 0) wsum[w] = s;
        __syncthreads();
        if (tid == 0) {
            float tot = 0.f;
            #pragma unroll
            for (int i = 0; i < 8; i++) tot += wsum[i];
            *losso = tot * lscale;
            g_done = 0;               // self-reset: deterministic per launch
        }
    }
}

extern "C" void kernel_launch(void* const* d_in, const int* in_sizes, int n_in,
                              void* d_out, int out_size)
{
    const float* ze  = (const float*)d_in[0];
    const float* emb = (const float*)d_in[1];
    int n = in_sizes[0] / DDIM;           // 524288
    float* out = (float*)d_out;

    long long nd = (long long)n * DDIM;
    float* idxo  = ((long long)out_size >= nd + n)     ? out + nd     : nullptr;
    float* losso = ((long long)out_size >= nd + n + 1) ? out + nd + n : nullptr;

    int grid = (n + TPT * TILES_PER_CTA - 1) / (TPT * TILES_PER_CTA);  // 1024

    cudaFuncSetAttribute((const void*)vq_main,
                         cudaFuncAttributeMaxDynamicSharedMemorySize,
                         SMEM_TOTAL);
    vq_main<<<grid, NTHREADS, SMEM_TOTAL>>>(ze, emb, out, idxo, losso, n,
                                            grid, 2.0f / (float)nd);
}